// round 16
// baseline (speedup 1.0000x reference)
#include <cuda_runtime.h>

#define HID 64
#define INCH 128
#define NMAX 50000
#define EMAX 1200000
#define EPS_RES 0.1f
#define BN_EPS 1e-5f

// ---------------- scratch (device globals; no allocation) ----------------
__device__ __align__(128) float  g_x0 [NMAX * HID];
__device__ __align__(128) float  g_b0 [NMAX * HID];   // fp32 ping
__device__ __align__(128) float  g_b1 [NMAX * HID];   // fp32 pong
__device__ __align__(128) float  g_t2 [NMAX * 32];
__device__ __align__(8) float2 g_sv[NMAX];   // (al[node], dinv[node])
__device__ float g_al[NMAX];
__device__ float g_ar[NMAX];
__device__ float g_dinv[NMAX];
__device__ int   g_deg[NMAX];    // raw in-edge count (no self-loop)
__device__ int   g_off[NMAX];    // start cursor; after scatter = end of range
__device__ int   g_ctr;
__device__ int   g_csrc[EMAX];
// BN stat slots: 0..2 = layers, 3 = head1, 4 = head2. [slot][0:64]=sum, [64:128]=sumsq
__device__ float g_stats2[5 * 128];

// scalar BN param for one column from a stats slot (slot<0 -> identity)
__device__ __forceinline__ float2 bn1(int slot, const float* gam, const float* bet,
                                      float invn, int c) {
    if (slot < 0) return make_float2(1.f, 0.f);
    float m   = g_stats2[slot * 128 + c] * invn;
    float var = g_stats2[slot * 128 + HID + c] * invn - m * m;
    float s   = gam[c] * rsqrtf(var + BN_EPS);
    return make_float2(s, bet[c] - m * s);
}

// ---------------- init ----------------
__global__ void k_init(int n) {
    int i = blockIdx.x * blockDim.x + threadIdx.x;
    if (i < n) g_deg[i] = 0;
    if (i < 5 * 128) g_stats2[i] = 0.f;
    if (i == 0) g_ctr = 0;
}

// ---------------- degree histogram: int4 edge loads (LSU-issue bound) ------------
__global__ void k_deg(const int* __restrict__ dst, int E) {
    int e0 = (blockIdx.x * blockDim.x + threadIdx.x) * 4;
    if (e0 + 4 <= E) {
        int4 d = *(const int4*)&dst[e0];
        atomicAdd(&g_deg[d.x], 1);
        atomicAdd(&g_deg[d.y], 1);
        atomicAdd(&g_deg[d.z], 1);
        atomicAdd(&g_deg[d.w], 1);
    } else {
        for (int e = e0; e < E; e++) atomicAdd(&g_deg[dst[e]], 1);
    }
}

// ---------------- CSR range allocation: warp-aggregated atomic, + dinv ------------
__global__ void k_off(int n) {
    int i = blockIdx.x * blockDim.x + threadIdx.x;
    int lane = threadIdx.x & 31;
    int v = (i < n) ? g_deg[i] : 0;          // raw in-edges
    if (i < n) g_dinv[i] = rsqrtf((float)(v + 1));   // +1 self-loop
    int pre = v;
#pragma unroll
    for (int o = 1; o < 32; o <<= 1) {
        int t = __shfl_up_sync(0xffffffffu, pre, o);
        if (lane >= o) pre += t;
    }
    int base = 0;
    if (lane == 31) base = atomicAdd(&g_ctr, pre);
    base = __shfl_sync(0xffffffffu, base, 31);
    if (i < n) g_off[i] = base + pre - v;
}

// ---------------- scatter: int4 edge loads, fused cursor --------------------------
__global__ void k_scatter(const int* __restrict__ src, const int* __restrict__ dst, int E) {
    int e0 = (blockIdx.x * blockDim.x + threadIdx.x) * 4;
    if (e0 + 4 <= E) {
        int4 s4 = *(const int4*)&src[e0];
        int4 d4 = *(const int4*)&dst[e0];
        int p0 = atomicAdd(&g_off[d4.x], 1);
        int p1 = atomicAdd(&g_off[d4.y], 1);
        int p2 = atomicAdd(&g_off[d4.z], 1);
        int p3 = atomicAdd(&g_off[d4.w], 1);
        g_csrc[p0] = s4.x;
        g_csrc[p1] = s4.y;
        g_csrc[p2] = s4.z;
        g_csrc[p3] = s4.w;
    } else {
        for (int e = e0; e < E; e++) {
            int pos = atomicAdd(&g_off[dst[e]], 1);
            g_csrc[pos] = src[e];
        }
    }
}

// ---------------- x0 = relu(x @ W_in + b_in); seed b0; fused layer-0 att dots -----
// K split into two 64-wide stages -> 32KB smem total (vs 64KB) for occupancy.
__global__ __launch_bounds__(256) void k_ingemm(
        const float* __restrict__ x, const float* __restrict__ W,
        const float* __restrict__ b,
        const float* __restrict__ attl, const float* __restrict__ attr, int n) {
    __shared__ float Ws[64 * HID];        // 16 KB, half-K [k][col]
    __shared__ float xs[64][64];          // 16 KB, rows x half-K
    int tid = threadIdx.x;
    int tx = tid & 15;
    int ty = tid >> 4;
    int row0 = blockIdx.x * 64;

    float acc[4][4];
#pragma unroll
    for (int i = 0; i < 4; i++)
#pragma unroll
        for (int j = 0; j < 4; j++) acc[i][j] = 0.f;

    int r0 = ty * 4, c0 = tx * 4;
    for (int s = 0; s < 2; s++) {
        if (s) __syncthreads();           // protect smem reuse between stages
        // load W half: rows s*64..s*64+63
        const float4* W4 = (const float4*)(W + s * 64 * HID);
        float4* Ws4 = (float4*)Ws;
        for (int i = tid; i < 64 * HID / 4; i += 256) Ws4[i] = W4[i];
        // load x half-tile: 64 rows x 64 k
        for (int i = tid; i < 64 * 16; i += 256) {
            int r = i >> 4, c4 = (i & 15) * 4;
            int gr = row0 + r;
            float4 v = (gr < n) ? *(const float4*)&x[gr * INCH + s * 64 + c4]
                                : make_float4(0.f, 0.f, 0.f, 0.f);
            *(float4*)&xs[r][c4] = v;
        }
        __syncthreads();
#pragma unroll 4
        for (int k = 0; k < 64; k++) {
            float4 wv = *(const float4*)&Ws[k * HID + c0];
            float a0 = xs[r0 + 0][k];
            float a1 = xs[r0 + 1][k];
            float a2 = xs[r0 + 2][k];
            float a3 = xs[r0 + 3][k];
            acc[0][0] += a0 * wv.x; acc[0][1] += a0 * wv.y; acc[0][2] += a0 * wv.z; acc[0][3] += a0 * wv.w;
            acc[1][0] += a1 * wv.x; acc[1][1] += a1 * wv.y; acc[1][2] += a1 * wv.z; acc[1][3] += a1 * wv.w;
            acc[2][0] += a2 * wv.x; acc[2][1] += a2 * wv.y; acc[2][2] += a2 * wv.z; acc[2][3] += a2 * wv.w;
            acc[3][0] += a3 * wv.x; acc[3][1] += a3 * wv.y; acc[3][2] += a3 * wv.z; acc[3][3] += a3 * wv.w;
        }
    }

    float4 bv  = *(const float4*)&b[c0];
    float4 alv = *(const float4*)&attl[c0];
    float4 arv = *(const float4*)&attr[c0];
#pragma unroll
    for (int i = 0; i < 4; i++) {
        int gr = row0 + r0 + i;
        bool ok = gr < n;
        float4 v;
        v.x = fmaxf(acc[i][0] + bv.x, 0.f);
        v.y = fmaxf(acc[i][1] + bv.y, 0.f);
        v.z = fmaxf(acc[i][2] + bv.z, 0.f);
        v.w = fmaxf(acc[i][3] + bv.w, 0.f);
        if (ok) {
            int base = gr * HID + c0;
            *(float4*)&g_x0[base] = v;
            *(float4*)&g_b0[base] = v;
        }
        // layer-0 attention dots (identity BN): reduce over the 16 tx lanes
        float pa = ok ? (v.x * alv.x + v.y * alv.y + v.z * alv.z + v.w * alv.w) : 0.f;
        float pr = ok ? (v.x * arv.x + v.y * arv.y + v.z * arv.z + v.w * arv.w) : 0.f;
#pragma unroll
        for (int o = 8; o; o >>= 1) {
            pa += __shfl_xor_sync(0xffffffffu, pa, o, 16);
            pr += __shfl_xor_sync(0xffffffffu, pr, o, 16);
        }
        if (tx == 0 && ok) { g_al[gr] = pa; g_ar[gr] = pr; }
    }
}

// ---------------- pack (al, dinv) -> g_sv for layer 0 (after stream join) --------
__global__ void k_pack(int n) {
    int i = blockIdx.x * blockDim.x + threadIdx.x;
    if (i < n) g_sv[i] = make_float2(g_al[i], g_dinv[i]);
}

// ---------------- per-node pre-pass (layers 1,2): al/ar projections ----------------
__global__ void k_node_pre(const float* __restrict__ attl,
                           const float* __restrict__ attr,
                           int slot, const float* __restrict__ gam,
                           const float* __restrict__ bet, float invn,
                           int inb, int n) {
    const float* bin = inb ? g_b1 : g_b0;
    int gt = blockIdx.x * blockDim.x + threadIdx.x;
    int node = gt >> 4, q = threadIdx.x & 15;
    unsigned gmask = 0xFFFFu << (threadIdx.x & 16);
    if (node >= n) return;
    int c0 = q * 4;
    int base = node * HID + c0;
    float4 y = *(const float4*)&bin[base];
    float2 p0 = bn1(slot, gam, bet, invn, c0 + 0);
    float2 p1 = bn1(slot, gam, bet, invn, c0 + 1);
    float2 p2 = bn1(slot, gam, bet, invn, c0 + 2);
    float2 p3 = bn1(slot, gam, bet, invn, c0 + 3);
    float4 h;
    h.x = y.x * p0.x + p0.y;
    h.y = y.y * p1.x + p1.y;
    h.z = y.z * p2.x + p2.y;
    h.w = y.w * p3.x + p3.y;
    float4 al4 = *(const float4*)&attl[c0];
    float4 ar4 = *(const float4*)&attr[c0];
    float a = h.x * al4.x + h.y * al4.y + h.z * al4.z + h.w * al4.w;
    float r = h.x * ar4.x + h.y * ar4.y + h.z * ar4.z + h.w * ar4.w;
#pragma unroll
    for (int o = 8; o; o >>= 1) {
        a += __shfl_xor_sync(gmask, a, o, 16);
        r += __shfl_xor_sync(gmask, r, o, 16);
    }
    if (q == 0) {
        g_ar[node] = r;
        g_sv[node] = make_float2(a, g_dinv[node]);
    }
}

// ---------------- aggregation: 16 threads/node, pipelined chunk setup -------------
__global__ __launch_bounds__(256) void k_agg(
        int slot_in, const float* __restrict__ gam, const float* __restrict__ bet,
        float invn, int slot_out, int inb, int n) {
    const float* bin  = inb ? g_b1 : g_b0;
    float*       bout = inb ? g_b0 : g_b1;
    __shared__ float ssum[HID], ssq[HID];
    int tid = threadIdx.x;
    if (tid < HID) { ssum[tid] = 0.f; ssq[tid] = 0.f; }
    __syncthreads();
    int node = blockIdx.x * 16 + (tid >> 4);
    int q = tid & 15;
    unsigned gmask = 0xFFFFu << (tid & 16);   // this 16-group's lanes
    if (node < n) {
        float4 acc = make_float4(0.f, 0.f, 0.f, 0.f);
        float wsum = 0.f;
        int cnt = g_deg[node];             // raw in-edges
        int p1 = g_off[node];              // post-scatter cursor = end
        int p0 = p1 - cnt;
        float dvd = g_dinv[node];
        float ard = g_ar[node];

        int p = p0 + q;
        int sq = (p < p1) ? __ldg(&g_csrc[p]) : 0;
        float2 sv = *(const float2*)&g_sv[sq];
        for (int chunk = p0; chunk < p1; chunk += 16) {
            float wq = (chunk + q < p1) ? tanhf(sv.x + ard) * sv.y * dvd : 0.f;
            int sb = sq * HID;
            int pn = chunk + 16 + q;
            sq = (pn < p1) ? __ldg(&g_csrc[pn]) : 0;
            sv = *(const float2*)&g_sv[sq];
            int m = min(16, p1 - chunk);
            if (m == 16) {
#pragma unroll 4
                for (int j = 0; j < 16; j++) {
                    int sbase = __shfl_sync(gmask, sb, j, 16);
                    float w   = __shfl_sync(gmask, wq, j, 16);
                    float4 hv = *(const float4*)&bin[sbase + q * 4];
                    acc.x += w * hv.x; acc.y += w * hv.y;
                    acc.z += w * hv.z; acc.w += w * hv.w;
                    wsum += w;
                }
            } else {
                for (int j = 0; j < m; j++) {
                    int sbase = __shfl_sync(gmask, sb, j, 16);
                    float w   = __shfl_sync(gmask, wq, j, 16);
                    float4 hv = *(const float4*)&bin[sbase + q * 4];
                    acc.x += w * hv.x; acc.y += w * hv.y;
                    acc.z += w * hv.z; acc.w += w * hv.w;
                    wsum += w;
                }
            }
        }
        // self-loop (fp32 row)
        float2 svn = g_sv[node];
        float ws = tanhf(svn.x + ard) * dvd * dvd;
        int base = node * HID + q * 4;
        float4 pv = *(const float4*)&bin[base];
        acc.x += ws * pv.x; acc.y += ws * pv.y;
        acc.z += ws * pv.z; acc.w += ws * pv.w;
        wsum += ws;
        // hoisted BN of h + residual + relu
        int c = q * 4;
        float2 b0 = bn1(slot_in, gam, bet, invn, c + 0);
        float2 b1 = bn1(slot_in, gam, bet, invn, c + 1);
        float2 b2 = bn1(slot_in, gam, bet, invn, c + 2);
        float2 b3 = bn1(slot_in, gam, bet, invn, c + 3);
        float4 x0v = *(const float4*)&g_x0[base];
        float4 v;
        v.x = fmaxf(b0.x * acc.x + b0.y * wsum + EPS_RES * x0v.x, 0.f);
        v.y = fmaxf(b1.x * acc.y + b1.y * wsum + EPS_RES * x0v.y, 0.f);
        v.z = fmaxf(b2.x * acc.z + b2.y * wsum + EPS_RES * x0v.z, 0.f);
        v.w = fmaxf(b3.x * acc.w + b3.y * wsum + EPS_RES * x0v.w, 0.f);
        *(float4*)&bout[base] = v;
        atomicAdd(&ssum[c + 0], v.x); atomicAdd(&ssum[c + 1], v.y);
        atomicAdd(&ssum[c + 2], v.z); atomicAdd(&ssum[c + 3], v.w);
        atomicAdd(&ssq[c + 0], v.x * v.x); atomicAdd(&ssq[c + 1], v.y * v.y);
        atomicAdd(&ssq[c + 2], v.z * v.z); atomicAdd(&ssq[c + 3], v.w * v.w);
    }
    __syncthreads();
    if (tid < HID) {
        atomicAdd(&g_stats2[slot_out * 128 + tid], ssum[tid]);
        atomicAdd(&g_stats2[slot_out * 128 + HID + tid], ssq[tid]);
    }
}

// ---------------- head1 (register-tiled): t1 = bn(y)[:bs] @ W1 + b1 ; stats -------
__global__ __launch_bounds__(256) void k_head1(
        const float* __restrict__ W1, const float* __restrict__ b1,
        int slot, const float* __restrict__ gam,
        const float* __restrict__ bet, float invn, int bs) {
    __shared__ float Ws[HID * HID];       // 16 KB [k][col]
    __shared__ float hs[64][HID + 4];     // padded: 16B-aligned rows, no conflicts
    __shared__ float2 pbn[HID];
    __shared__ float ssum[HID], ssq[HID];
    int tid = threadIdx.x;
    int tx = tid & 15, ty = tid >> 4;
    if (tid < HID) {
        pbn[tid] = bn1(slot, gam, bet, invn, tid);
        ssum[tid] = 0.f; ssq[tid] = 0.f;
    }
    __syncthreads();
    const float4* W14 = (const float4*)W1;
    float4* Ws4 = (float4*)Ws;
    for (int i = tid; i < HID * HID / 4; i += 256) Ws4[i] = W14[i];
    int row0 = blockIdx.x * 64;
    for (int i = tid; i < 64 * 16; i += 256) {
        int r = i >> 4, c4 = (i & 15) * 4;
        int gr = row0 + r;
        float4 y = (gr < bs) ? *(const float4*)&g_b1[gr * HID + c4]
                             : make_float4(0.f, 0.f, 0.f, 0.f);
        float2 q0 = pbn[c4 + 0], q1 = pbn[c4 + 1], q2 = pbn[c4 + 2], q3 = pbn[c4 + 3];
        float4 h;
        h.x = (gr < bs) ? y.x * q0.x + q0.y : 0.f;
        h.y = (gr < bs) ? y.y * q1.x + q1.y : 0.f;
        h.z = (gr < bs) ? y.z * q2.x + q2.y : 0.f;
        h.w = (gr < bs) ? y.w * q3.x + q3.y : 0.f;
        *(float4*)&hs[r][c4] = h;
    }
    __syncthreads();

    float acc[4][4];
#pragma unroll
    for (int i = 0; i < 4; i++)
#pragma unroll
        for (int j = 0; j < 4; j++) acc[i][j] = 0.f;
    int r0 = ty * 4, c0 = tx * 4;
#pragma unroll 4
    for (int k = 0; k < HID; k++) {
        float4 wv = *(const float4*)&Ws[k * HID + c0];
        float a0 = hs[r0 + 0][k];
        float a1 = hs[r0 + 1][k];
        float a2 = hs[r0 + 2][k];
        float a3 = hs[r0 + 3][k];
        acc[0][0] += a0 * wv.x; acc[0][1] += a0 * wv.y; acc[0][2] += a0 * wv.z; acc[0][3] += a0 * wv.w;
        acc[1][0] += a1 * wv.x; acc[1][1] += a1 * wv.y; acc[1][2] += a1 * wv.z; acc[1][3] += a1 * wv.w;
        acc[2][0] += a2 * wv.x; acc[2][1] += a2 * wv.y; acc[2][2] += a2 * wv.z; acc[2][3] += a2 * wv.w;
        acc[3][0] += a3 * wv.x; acc[3][1] += a3 * wv.y; acc[3][2] += a3 * wv.z; acc[3][3] += a3 * wv.w;
    }

    float4 bv = *(const float4*)&b1[c0];
    float cs[4] = {0.f, 0.f, 0.f, 0.f};
    float cq[4] = {0.f, 0.f, 0.f, 0.f};
#pragma unroll
    for (int i = 0; i < 4; i++) {
        int gr = row0 + r0 + i;
        if (gr >= bs) break;
        float4 v;
        v.x = acc[i][0] + bv.x;
        v.y = acc[i][1] + bv.y;
        v.z = acc[i][2] + bv.z;
        v.w = acc[i][3] + bv.w;
        *(float4*)&g_b0[gr * HID + c0] = v;
        cs[0] += v.x; cs[1] += v.y; cs[2] += v.z; cs[3] += v.w;
        cq[0] += v.x * v.x; cq[1] += v.y * v.y; cq[2] += v.z * v.z; cq[3] += v.w * v.w;
    }
#pragma unroll
    for (int j = 0; j < 4; j++) {
        atomicAdd(&ssum[c0 + j], cs[j]);
        atomicAdd(&ssq[c0 + j], cq[j]);
    }
    __syncthreads();
    if (tid < HID) {
        atomicAdd(&g_stats2[3 * 128 + tid], ssum[tid]);
        atomicAdd(&g_stats2[3 * 128 + HID + tid], ssq[tid]);
    }
}

// ---------------- head: t2 = relu(bn(t1)) @ W2 + b2 ; stats (g_b0 -> g_t2) --------
__global__ void k_head2(const float* __restrict__ W2, const float* __restrict__ b2,
                        int slot, const float* __restrict__ gam,
                        const float* __restrict__ bet, float invn, int bs) {
    __shared__ float Ws[HID * 32];
    __shared__ float us[8][HID];
    __shared__ float ssum[32], ssq[32];
    int tx = threadIdx.x, ty = threadIdx.y;   // 32 x 8
    int tid = ty * 32 + tx;
    for (int i = tid; i < HID * 32; i += 256) Ws[i] = W2[i];
    int row = blockIdx.x * 8 + ty;
    float2 pa = bn1(slot, gam, bet, invn, tx);
    float2 pb = bn1(slot, gam, bet, invn, 32 + tx);
    if (row < bs) {
        float v0 = g_b0[row * HID + tx]      * pa.x + pa.y;
        float v1 = g_b0[row * HID + 32 + tx] * pb.x + pb.y;
        us[ty][tx] = fmaxf(v0, 0.f);
        us[ty][32 + tx] = fmaxf(v1, 0.f);
    } else { us[ty][tx] = 0.f; us[ty][32 + tx] = 0.f; }
    if (tid < 32) { ssum[tid] = 0.f; ssq[tid] = 0.f; }
    __syncthreads();
    float acc = b2[tx];
#pragma unroll
    for (int k = 0; k < HID; k++) acc += us[ty][k] * Ws[k * 32 + tx];
    if (row < bs) g_t2[row * 32 + tx] = acc; else acc = 0.f;
    atomicAdd(&ssum[tx], acc);
    atomicAdd(&ssq[tx], acc * acc);
    __syncthreads();
    if (tid < 32) {
        atomicAdd(&g_stats2[4 * 128 + tid], ssum[tid]);
        atomicAdd(&g_stats2[4 * 128 + HID + tid], ssq[tid]);
    }
}

// ---------------- head: out = relu(bn(t2)) @ W3 + b3 ----------------
__global__ void k_head3(const float* __restrict__ W3, const float* __restrict__ b3,
                        int slot, const float* __restrict__ gam,
                        const float* __restrict__ bet, float invn,
                        float* __restrict__ out, int bs) {
    int gt = blockIdx.x * blockDim.x + threadIdx.x;
    int row = gt >> 5, lane = threadIdx.x & 31;
    if (row >= bs) return;
    float2 p = bn1(slot, gam, bet, invn, lane);
    float v = g_t2[row * 32 + lane] * p.x + p.y;
    v = fmaxf(v, 0.f) * W3[lane];
#pragma unroll
    for (int o = 16; o; o >>= 1) v += __shfl_xor_sync(0xffffffffu, v, o);
    if (lane == 0) out[row] = v + b3[0];
}

extern "C" void kernel_launch(void* const* d_in, const int* in_sizes, int n_in,
                              void* d_out, int out_size) {
    const float* x    = (const float*)d_in[0];
    const int*   ei   = (const int*)d_in[1];
    int E = in_sizes[1] / 2;
    int n = in_sizes[0] / INCH;
    const float* W_in  = (const float*)d_in[3];
    const float* b_in  = (const float*)d_in[4];
    const float* att_l = (const float*)d_in[5];
    const float* att_r = (const float*)d_in[6];
    const float* bn_g  = (const float*)d_in[7];
    const float* bn_b  = (const float*)d_in[8];
    const float* W1  = (const float*)d_in[9];
    const float* b1  = (const float*)d_in[10];
    const float* g1  = (const float*)d_in[11];
    const float* be1 = (const float*)d_in[12];
    const float* W2  = (const float*)d_in[13];
    const float* b2  = (const float*)d_in[14];
    const float* g2  = (const float*)d_in[15];
    const float* be2 = (const float*)d_in[16];
    const float* W3  = (const float*)d_in[17];
    const float* b3  = (const float*)d_in[18];
    const int* src = ei;
    const int* dst = ei + E;
    int bs = out_size;
    float invn = 1.0f / n, invbs = 1.0f / bs;

    static cudaStream_t s1 = nullptr;
    static cudaEvent_t ev_fork = nullptr, ev_join = nullptr;
    if (s1 == nullptr) {
        cudaStreamCreateWithFlags(&s1, cudaStreamNonBlocking);
        cudaEventCreateWithFlags(&ev_fork, cudaEventDisableTiming);
        cudaEventCreateWithFlags(&ev_join, cudaEventDisableTiming);
    }

    // Fork: CSR build on s1, input GEMM (+ fused layer-0 att dots) on main stream.
    cudaEventRecord(ev_fork, 0);
    cudaStreamWaitEvent(s1, ev_fork, 0);

    k_init   <<<(n + 255) / 256, 256, 0, s1>>>(n);
    k_deg    <<<((E + 3) / 4 + 255) / 256, 256, 0, s1>>>(dst, E);
    k_off    <<<(n + 255) / 256, 256, 0, s1>>>(n);
    k_scatter<<<((E + 3) / 4 + 255) / 256, 256, 0, s1>>>(src, dst, E);
    cudaEventRecord(ev_join, s1);

    k_ingemm<<<(n + 63) / 64, 256>>>(x, W_in, b_in, att_l, att_r, n);

    cudaStreamWaitEvent(0, ev_join, 0);
    k_pack<<<(n + 255) / 256, 256>>>(n);   // (al from ingemm, dinv from k_off)

    for (int l = 0; l < 3; l++) {
        int slot_in = l - 1;               // -1 = identity BN (layer 0)
        const float* gam = bn_g + (l > 0 ? (l - 1) * HID : 0);
        const float* bet = bn_b + (l > 0 ? (l - 1) * HID : 0);
        int inb = l & 1;
        if (l > 0)
            k_node_pre<<<(n * 16 + 255) / 256, 256>>>(
                att_l + l * HID, att_r + l * HID, slot_in, gam, bet, invn, inb, n);
        k_agg<<<(n + 15) / 16, 256>>>(slot_in, gam, bet, invn, l, inb, n);
    }

    // final buffer is g_b1 (agg2: in=0 -> out=1)
    k_head1<<<(bs + 63) / 64, 256>>>(W1, b1, 2, bn_g + 2 * HID, bn_b + 2 * HID, invn, bs);
    k_head2<<<(bs + 7) / 8, dim3(32, 8)>>>(W2, b2, 3, g1, be1, invbs, bs);
    k_head3<<<(bs * 32 + 255) / 256, 256>>>(W3, b3, 4, g2, be2, invbs, (float*)d_out, bs);
}

// round 17
// speedup vs baseline: 1.0352x; 1.0352x over previous
#include <cuda_runtime.h>

#define HID 64
#define INCH 128
#define NMAX 50000
#define EMAX 1200000
#define EPS_RES 0.1f
#define BN_EPS 1e-5f

// ---------------- scratch (device globals; no allocation) ----------------
__device__ __align__(128) float  g_x0 [NMAX * HID];
__device__ __align__(128) float  g_b0 [NMAX * HID];   // fp32 ping
__device__ __align__(128) float  g_b1 [NMAX * HID];   // fp32 pong
__device__ __align__(128) float  g_t2 [NMAX * 32];
__device__ __align__(8) float2 g_sv[NMAX];   // (al[node], dinv[node])
__device__ float g_ar[NMAX];
__device__ float g_dinv[NMAX];
__device__ int   g_deg[NMAX];    // raw in-edge count (no self-loop)
__device__ int   g_off[NMAX];    // start cursor; after scatter = end of range
__device__ int   g_ctr;
__device__ int   g_csrc[EMAX];
// BN stat slots: 0..2 = layers, 3 = head1, 4 = head2. [slot][0:64]=sum, [64:128]=sumsq
__device__ float g_stats2[5 * 128];

// scalar BN param for one column from a stats slot (slot<0 -> identity)
__device__ __forceinline__ float2 bn1(int slot, const float* gam, const float* bet,
                                      float invn, int c) {
    if (slot < 0) return make_float2(1.f, 0.f);
    float m   = g_stats2[slot * 128 + c] * invn;
    float var = g_stats2[slot * 128 + HID + c] * invn - m * m;
    float s   = gam[c] * rsqrtf(var + BN_EPS);
    return make_float2(s, bet[c] - m * s);
}

// ---------------- init ----------------
__global__ void k_init(int n) {
    int i = blockIdx.x * blockDim.x + threadIdx.x;
    if (i < n) g_deg[i] = 0;
    if (i < 5 * 128) g_stats2[i] = 0.f;
    if (i == 0) g_ctr = 0;
}

// ---------------- degree histogram: int4 edge loads ----------------
__global__ void k_deg(const int* __restrict__ dst, int E) {
    int e0 = (blockIdx.x * blockDim.x + threadIdx.x) * 4;
    if (e0 + 4 <= E) {
        int4 d = *(const int4*)&dst[e0];
        atomicAdd(&g_deg[d.x], 1);
        atomicAdd(&g_deg[d.y], 1);
        atomicAdd(&g_deg[d.z], 1);
        atomicAdd(&g_deg[d.w], 1);
    } else {
        for (int e = e0; e < E; e++) atomicAdd(&g_deg[dst[e]], 1);
    }
}

// ---------------- CSR range allocation: warp-aggregated atomic, + dinv ------------
// Also writes g_sv[i].y = dinv (the .x field is written by k_ingemm on the
// other stream — disjoint 4-byte words, no race).
__global__ void k_off(int n) {
    int i = blockIdx.x * blockDim.x + threadIdx.x;
    int lane = threadIdx.x & 31;
    int v = (i < n) ? g_deg[i] : 0;          // raw in-edges
    float dv = rsqrtf((float)(v + 1));       // +1 self-loop
    if (i < n) { g_dinv[i] = dv; g_sv[i].y = dv; }
    int pre = v;
#pragma unroll
    for (int o = 1; o < 32; o <<= 1) {
        int t = __shfl_up_sync(0xffffffffu, pre, o);
        if (lane >= o) pre += t;
    }
    int base = 0;
    if (lane == 31) base = atomicAdd(&g_ctr, pre);
    base = __shfl_sync(0xffffffffu, base, 31);
    if (i < n) g_off[i] = base + pre - v;
}

// ---------------- scatter: int4 edge loads, fused cursor --------------------------
__global__ void k_scatter(const int* __restrict__ src, const int* __restrict__ dst, int E) {
    int e0 = (blockIdx.x * blockDim.x + threadIdx.x) * 4;
    if (e0 + 4 <= E) {
        int4 s4 = *(const int4*)&src[e0];
        int4 d4 = *(const int4*)&dst[e0];
        int p0 = atomicAdd(&g_off[d4.x], 1);
        int p1 = atomicAdd(&g_off[d4.y], 1);
        int p2 = atomicAdd(&g_off[d4.z], 1);
        int p3 = atomicAdd(&g_off[d4.w], 1);
        g_csrc[p0] = s4.x;
        g_csrc[p1] = s4.y;
        g_csrc[p2] = s4.z;
        g_csrc[p3] = s4.w;
    } else {
        for (int e = e0; e < E; e++) {
            int pos = atomicAdd(&g_off[dst[e]], 1);
            g_csrc[pos] = src[e];
        }
    }
}

// ---------------- x0 = relu(x @ W_in + b_in); seed b0; fused layer-0 att dots -----
// Writes g_sv[gr].x = al (dinv field owned by k_off on the other stream).
__global__ __launch_bounds__(256) void k_ingemm(
        const float* __restrict__ x, const float* __restrict__ W,
        const float* __restrict__ b,
        const float* __restrict__ attl, const float* __restrict__ attr, int n) {
    __shared__ float Ws[64 * HID];        // 16 KB, half-K [k][col]
    __shared__ float xs[64][64];          // 16 KB, rows x half-K
    int tid = threadIdx.x;
    int tx = tid & 15;
    int ty = tid >> 4;
    int row0 = blockIdx.x * 64;

    float acc[4][4];
#pragma unroll
    for (int i = 0; i < 4; i++)
#pragma unroll
        for (int j = 0; j < 4; j++) acc[i][j] = 0.f;

    int r0 = ty * 4, c0 = tx * 4;
    for (int s = 0; s < 2; s++) {
        if (s) __syncthreads();           // protect smem reuse between stages
        const float4* W4 = (const float4*)(W + s * 64 * HID);
        float4* Ws4 = (float4*)Ws;
        for (int i = tid; i < 64 * HID / 4; i += 256) Ws4[i] = W4[i];
        for (int i = tid; i < 64 * 16; i += 256) {
            int r = i >> 4, c4 = (i & 15) * 4;
            int gr = row0 + r;
            float4 v = (gr < n) ? *(const float4*)&x[gr * INCH + s * 64 + c4]
                                : make_float4(0.f, 0.f, 0.f, 0.f);
            *(float4*)&xs[r][c4] = v;
        }
        __syncthreads();
#pragma unroll 4
        for (int k = 0; k < 64; k++) {
            float4 wv = *(const float4*)&Ws[k * HID + c0];
            float a0 = xs[r0 + 0][k];
            float a1 = xs[r0 + 1][k];
            float a2 = xs[r0 + 2][k];
            float a3 = xs[r0 + 3][k];
            acc[0][0] += a0 * wv.x; acc[0][1] += a0 * wv.y; acc[0][2] += a0 * wv.z; acc[0][3] += a0 * wv.w;
            acc[1][0] += a1 * wv.x; acc[1][1] += a1 * wv.y; acc[1][2] += a1 * wv.z; acc[1][3] += a1 * wv.w;
            acc[2][0] += a2 * wv.x; acc[2][1] += a2 * wv.y; acc[2][2] += a2 * wv.z; acc[2][3] += a2 * wv.w;
            acc[3][0] += a3 * wv.x; acc[3][1] += a3 * wv.y; acc[3][2] += a3 * wv.z; acc[3][3] += a3 * wv.w;
        }
    }

    float4 bv  = *(const float4*)&b[c0];
    float4 alv = *(const float4*)&attl[c0];
    float4 arv = *(const float4*)&attr[c0];
#pragma unroll
    for (int i = 0; i < 4; i++) {
        int gr = row0 + r0 + i;
        bool ok = gr < n;
        float4 v;
        v.x = fmaxf(acc[i][0] + bv.x, 0.f);
        v.y = fmaxf(acc[i][1] + bv.y, 0.f);
        v.z = fmaxf(acc[i][2] + bv.z, 0.f);
        v.w = fmaxf(acc[i][3] + bv.w, 0.f);
        if (ok) {
            int base = gr * HID + c0;
            *(float4*)&g_x0[base] = v;
            *(float4*)&g_b0[base] = v;
        }
        // layer-0 attention dots (identity BN): reduce over the 16 tx lanes
        float pa = ok ? (v.x * alv.x + v.y * alv.y + v.z * alv.z + v.w * alv.w) : 0.f;
        float pr = ok ? (v.x * arv.x + v.y * arv.y + v.z * arv.z + v.w * arv.w) : 0.f;
#pragma unroll
        for (int o = 8; o; o >>= 1) {
            pa += __shfl_xor_sync(0xffffffffu, pa, o, 16);
            pr += __shfl_xor_sync(0xffffffffu, pr, o, 16);
        }
        if (tx == 0 && ok) { g_ar[gr] = pa == pa ? pa : pa; g_ar[gr] = pr; g_sv[gr].x = pa; }
    }
}

// ---------------- per-node pre-pass (layers 1,2): al/ar projections ----------------
__global__ void k_node_pre(const float* __restrict__ attl,
                           const float* __restrict__ attr,
                           int slot, const float* __restrict__ gam,
                           const float* __restrict__ bet, float invn,
                           int inb, int n) {
    const float* bin = inb ? g_b1 : g_b0;
    int gt = blockIdx.x * blockDim.x + threadIdx.x;
    int node = gt >> 4, q = threadIdx.x & 15;
    unsigned gmask = 0xFFFFu << (threadIdx.x & 16);
    if (node >= n) return;
    int c0 = q * 4;
    int base = node * HID + c0;
    float4 y = *(const float4*)&bin[base];
    float2 p0 = bn1(slot, gam, bet, invn, c0 + 0);
    float2 p1 = bn1(slot, gam, bet, invn, c0 + 1);
    float2 p2 = bn1(slot, gam, bet, invn, c0 + 2);
    float2 p3 = bn1(slot, gam, bet, invn, c0 + 3);
    float4 h;
    h.x = y.x * p0.x + p0.y;
    h.y = y.y * p1.x + p1.y;
    h.z = y.z * p2.x + p2.y;
    h.w = y.w * p3.x + p3.y;
    float4 al4 = *(const float4*)&attl[c0];
    float4 ar4 = *(const float4*)&attr[c0];
    float a = h.x * al4.x + h.y * al4.y + h.z * al4.z + h.w * al4.w;
    float r = h.x * ar4.x + h.y * ar4.y + h.z * ar4.z + h.w * ar4.w;
#pragma unroll
    for (int o = 8; o; o >>= 1) {
        a += __shfl_xor_sync(gmask, a, o, 16);
        r += __shfl_xor_sync(gmask, r, o, 16);
    }
    if (q == 0) {
        g_ar[node] = r;
        g_sv[node] = make_float2(a, g_dinv[node]);
    }
}

// ---------------- aggregation: 16 threads/node, FULL-unroll inner (MLP 16) --------
__global__ __launch_bounds__(256) void k_agg(
        int slot_in, const float* __restrict__ gam, const float* __restrict__ bet,
        float invn, int slot_out, int inb, int n) {
    const float* bin  = inb ? g_b1 : g_b0;
    float*       bout = inb ? g_b0 : g_b1;
    __shared__ float ssum[HID], ssq[HID];
    int tid = threadIdx.x;
    if (tid < HID) { ssum[tid] = 0.f; ssq[tid] = 0.f; }
    __syncthreads();
    int node = blockIdx.x * 16 + (tid >> 4);
    int q = tid & 15;
    unsigned gmask = 0xFFFFu << (tid & 16);   // this 16-group's lanes
    if (node < n) {
        float4 acc = make_float4(0.f, 0.f, 0.f, 0.f);
        float wsum = 0.f;
        int cnt = g_deg[node];             // raw in-edges
        int p1 = g_off[node];              // post-scatter cursor = end
        int p0 = p1 - cnt;
        float dvd = g_dinv[node];
        float ard = g_ar[node];

        int p = p0 + q;
        int sq = (p < p1) ? __ldg(&g_csrc[p]) : 0;
        float2 sv = *(const float2*)&g_sv[sq];
        for (int chunk = p0; chunk < p1; chunk += 16) {
            float wq = (chunk + q < p1) ? tanhf(sv.x + ard) * sv.y * dvd : 0.f;
            int sb = sq * HID;
            int pn = chunk + 16 + q;
            sq = (pn < p1) ? __ldg(&g_csrc[pn]) : 0;
            sv = *(const float2*)&g_sv[sq];
            int m = min(16, p1 - chunk);
            if (m == 16) {
#pragma unroll
                for (int j = 0; j < 16; j++) {
                    int sbase = __shfl_sync(gmask, sb, j, 16);
                    float w   = __shfl_sync(gmask, wq, j, 16);
                    float4 hv = *(const float4*)&bin[sbase + q * 4];
                    acc.x += w * hv.x; acc.y += w * hv.y;
                    acc.z += w * hv.z; acc.w += w * hv.w;
                    wsum += w;
                }
            } else {
                for (int j = 0; j < m; j++) {
                    int sbase = __shfl_sync(gmask, sb, j, 16);
                    float w   = __shfl_sync(gmask, wq, j, 16);
                    float4 hv = *(const float4*)&bin[sbase + q * 4];
                    acc.x += w * hv.x; acc.y += w * hv.y;
                    acc.z += w * hv.z; acc.w += w * hv.w;
                    wsum += w;
                }
            }
        }
        // self-loop (fp32 row)
        float2 svn = g_sv[node];
        float ws = tanhf(svn.x + ard) * dvd * dvd;
        int base = node * HID + q * 4;
        float4 pv = *(const float4*)&bin[base];
        acc.x += ws * pv.x; acc.y += ws * pv.y;
        acc.z += ws * pv.z; acc.w += ws * pv.w;
        wsum += ws;
        // hoisted BN of h + residual + relu
        int c = q * 4;
        float2 b0 = bn1(slot_in, gam, bet, invn, c + 0);
        float2 b1 = bn1(slot_in, gam, bet, invn, c + 1);
        float2 b2 = bn1(slot_in, gam, bet, invn, c + 2);
        float2 b3 = bn1(slot_in, gam, bet, invn, c + 3);
        float4 x0v = *(const float4*)&g_x0[base];
        float4 v;
        v.x = fmaxf(b0.x * acc.x + b0.y * wsum + EPS_RES * x0v.x, 0.f);
        v.y = fmaxf(b1.x * acc.y + b1.y * wsum + EPS_RES * x0v.y, 0.f);
        v.z = fmaxf(b2.x * acc.z + b2.y * wsum + EPS_RES * x0v.z, 0.f);
        v.w = fmaxf(b3.x * acc.w + b3.y * wsum + EPS_RES * x0v.w, 0.f);
        *(float4*)&bout[base] = v;
        atomicAdd(&ssum[c + 0], v.x); atomicAdd(&ssum[c + 1], v.y);
        atomicAdd(&ssum[c + 2], v.z); atomicAdd(&ssum[c + 3], v.w);
        atomicAdd(&ssq[c + 0], v.x * v.x); atomicAdd(&ssq[c + 1], v.y * v.y);
        atomicAdd(&ssq[c + 2], v.z * v.z); atomicAdd(&ssq[c + 3], v.w * v.w);
    }
    __syncthreads();
    if (tid < HID) {
        atomicAdd(&g_stats2[slot_out * 128 + tid], ssum[tid]);
        atomicAdd(&g_stats2[slot_out * 128 + HID + tid], ssq[tid]);
    }
}

// ---------------- head1 (register-tiled): t1 = bn(y)[:bs] @ W1 + b1 ; stats -------
__global__ __launch_bounds__(256) void k_head1(
        const float* __restrict__ W1, const float* __restrict__ b1,
        int slot, const float* __restrict__ gam,
        const float* __restrict__ bet, float invn, int bs) {
    __shared__ float Ws[HID * HID];       // 16 KB [k][col]
    __shared__ float hs[64][HID + 4];     // padded: 16B-aligned rows, no conflicts
    __shared__ float2 pbn[HID];
    __shared__ float ssum[HID], ssq[HID];
    int tid = threadIdx.x;
    int tx = tid & 15, ty = tid >> 4;
    if (tid < HID) {
        pbn[tid] = bn1(slot, gam, bet, invn, tid);
        ssum[tid] = 0.f; ssq[tid] = 0.f;
    }
    __syncthreads();
    const float4* W14 = (const float4*)W1;
    float4* Ws4 = (float4*)Ws;
    for (int i = tid; i < HID * HID / 4; i += 256) Ws4[i] = W14[i];
    int row0 = blockIdx.x * 64;
    for (int i = tid; i < 64 * 16; i += 256) {
        int r = i >> 4, c4 = (i & 15) * 4;
        int gr = row0 + r;
        float4 y = (gr < bs) ? *(const float4*)&g_b1[gr * HID + c4]
                             : make_float4(0.f, 0.f, 0.f, 0.f);
        float2 q0 = pbn[c4 + 0], q1 = pbn[c4 + 1], q2 = pbn[c4 + 2], q3 = pbn[c4 + 3];
        float4 h;
        h.x = (gr < bs) ? y.x * q0.x + q0.y : 0.f;
        h.y = (gr < bs) ? y.y * q1.x + q1.y : 0.f;
        h.z = (gr < bs) ? y.z * q2.x + q2.y : 0.f;
        h.w = (gr < bs) ? y.w * q3.x + q3.y : 0.f;
        *(float4*)&hs[r][c4] = h;
    }
    __syncthreads();

    float acc[4][4];
#pragma unroll
    for (int i = 0; i < 4; i++)
#pragma unroll
        for (int j = 0; j < 4; j++) acc[i][j] = 0.f;
    int r0 = ty * 4, c0 = tx * 4;
#pragma unroll 4
    for (int k = 0; k < HID; k++) {
        float4 wv = *(const float4*)&Ws[k * HID + c0];
        float a0 = hs[r0 + 0][k];
        float a1 = hs[r0 + 1][k];
        float a2 = hs[r0 + 2][k];
        float a3 = hs[r0 + 3][k];
        acc[0][0] += a0 * wv.x; acc[0][1] += a0 * wv.y; acc[0][2] += a0 * wv.z; acc[0][3] += a0 * wv.w;
        acc[1][0] += a1 * wv.x; acc[1][1] += a1 * wv.y; acc[1][2] += a1 * wv.z; acc[1][3] += a1 * wv.w;
        acc[2][0] += a2 * wv.x; acc[2][1] += a2 * wv.y; acc[2][2] += a2 * wv.z; acc[2][3] += a2 * wv.w;
        acc[3][0] += a3 * wv.x; acc[3][1] += a3 * wv.y; acc[3][2] += a3 * wv.z; acc[3][3] += a3 * wv.w;
    }

    float4 bv = *(const float4*)&b1[c0];
    float cs[4] = {0.f, 0.f, 0.f, 0.f};
    float cq[4] = {0.f, 0.f, 0.f, 0.f};
#pragma unroll
    for (int i = 0; i < 4; i++) {
        int gr = row0 + r0 + i;
        if (gr >= bs) break;
        float4 v;
        v.x = acc[i][0] + bv.x;
        v.y = acc[i][1] + bv.y;
        v.z = acc[i][2] + bv.z;
        v.w = acc[i][3] + bv.w;
        *(float4*)&g_b0[gr * HID + c0] = v;
        cs[0] += v.x; cs[1] += v.y; cs[2] += v.z; cs[3] += v.w;
        cq[0] += v.x * v.x; cq[1] += v.y * v.y; cq[2] += v.z * v.z; cq[3] += v.w * v.w;
    }
#pragma unroll
    for (int j = 0; j < 4; j++) {
        atomicAdd(&ssum[c0 + j], cs[j]);
        atomicAdd(&ssq[c0 + j], cq[j]);
    }
    __syncthreads();
    if (tid < HID) {
        atomicAdd(&g_stats2[3 * 128 + tid], ssum[tid]);
        atomicAdd(&g_stats2[3 * 128 + HID + tid], ssq[tid]);
    }
}

// ---------------- head: t2 = relu(bn(t1)) @ W2 + b2 ; stats (g_b0 -> g_t2) --------
__global__ void k_head2(const float* __restrict__ W2, const float* __restrict__ b2,
                        int slot, const float* __restrict__ gam,
                        const float* __restrict__ bet, float invn, int bs) {
    __shared__ float Ws[HID * 32];
    __shared__ float us[8][HID];
    __shared__ float ssum[32], ssq[32];
    int tx = threadIdx.x, ty = threadIdx.y;   // 32 x 8
    int tid = ty * 32 + tx;
    for (int i = tid; i < HID * 32; i += 256) Ws[i] = W2[i];
    int row = blockIdx.x * 8 + ty;
    float2 pa = bn1(slot, gam, bet, invn, tx);
    float2 pb = bn1(slot, gam, bet, invn, 32 + tx);
    if (row < bs) {
        float v0 = g_b0[row * HID + tx]      * pa.x + pa.y;
        float v1 = g_b0[row * HID + 32 + tx] * pb.x + pb.y;
        us[ty][tx] = fmaxf(v0, 0.f);
        us[ty][32 + tx] = fmaxf(v1, 0.f);
    } else { us[ty][tx] = 0.f; us[ty][32 + tx] = 0.f; }
    if (tid < 32) { ssum[tid] = 0.f; ssq[tid] = 0.f; }
    __syncthreads();
    float acc = b2[tx];
#pragma unroll
    for (int k = 0; k < HID; k++) acc += us[ty][k] * Ws[k * 32 + tx];
    if (row < bs) g_t2[row * 32 + tx] = acc; else acc = 0.f;
    atomicAdd(&ssum[tx], acc);
    atomicAdd(&ssq[tx], acc * acc);
    __syncthreads();
    if (tid < 32) {
        atomicAdd(&g_stats2[4 * 128 + tid], ssum[tid]);
        atomicAdd(&g_stats2[4 * 128 + HID + tid], ssq[tid]);
    }
}

// ---------------- head: out = relu(bn(t2)) @ W3 + b3 ----------------
__global__ void k_head3(const float* __restrict__ W3, const float* __restrict__ b3,
                        int slot, const float* __restrict__ gam,
                        const float* __restrict__ bet, float invn,
                        float* __restrict__ out, int bs) {
    int gt = blockIdx.x * blockDim.x + threadIdx.x;
    int row = gt >> 5, lane = threadIdx.x & 31;
    if (row >= bs) return;
    float2 p = bn1(slot, gam, bet, invn, lane);
    float v = g_t2[row * 32 + lane] * p.x + p.y;
    v = fmaxf(v, 0.f) * W3[lane];
#pragma unroll
    for (int o = 16; o; o >>= 1) v += __shfl_xor_sync(0xffffffffu, v, o);
    if (lane == 0) out[row] = v + b3[0];
}

extern "C" void kernel_launch(void* const* d_in, const int* in_sizes, int n_in,
                              void* d_out, int out_size) {
    const float* x    = (const float*)d_in[0];
    const int*   ei   = (const int*)d_in[1];
    int E = in_sizes[1] / 2;
    int n = in_sizes[0] / INCH;
    const float* W_in  = (const float*)d_in[3];
    const float* b_in  = (const float*)d_in[4];
    const float* att_l = (const float*)d_in[5];
    const float* att_r = (const float*)d_in[6];
    const float* bn_g  = (const float*)d_in[7];
    const float* bn_b  = (const float*)d_in[8];
    const float* W1  = (const float*)d_in[9];
    const float* b1  = (const float*)d_in[10];
    const float* g1  = (const float*)d_in[11];
    const float* be1 = (const float*)d_in[12];
    const float* W2  = (const float*)d_in[13];
    const float* b2  = (const float*)d_in[14];
    const float* g2  = (const float*)d_in[15];
    const float* be2 = (const float*)d_in[16];
    const float* W3  = (const float*)d_in[17];
    const float* b3  = (const float*)d_in[18];
    const int* src = ei;
    const int* dst = ei + E;
    int bs = out_size;
    float invn = 1.0f / n, invbs = 1.0f / bs;

    static cudaStream_t s1 = nullptr;
    static cudaEvent_t ev_fork = nullptr, ev_join = nullptr;
    if (s1 == nullptr) {
        cudaStreamCreateWithFlags(&s1, cudaStreamNonBlocking);
        cudaEventCreateWithFlags(&ev_fork, cudaEventDisableTiming);
        cudaEventCreateWithFlags(&ev_join, cudaEventDisableTiming);
    }

    // Fork: CSR build on s1, input GEMM (+ fused layer-0 att dots) on main stream.
    cudaEventRecord(ev_fork, 0);
    cudaStreamWaitEvent(s1, ev_fork, 0);

    k_init   <<<(n + 255) / 256, 256, 0, s1>>>(n);
    k_deg    <<<((E + 3) / 4 + 255) / 256, 256, 0, s1>>>(dst, E);
    k_off    <<<(n + 255) / 256, 256, 0, s1>>>(n);
    k_scatter<<<((E + 3) / 4 + 255) / 256, 256, 0, s1>>>(src, dst, E);
    cudaEventRecord(ev_join, s1);

    k_ingemm<<<(n + 63) / 64, 256>>>(x, W_in, b_in, att_l, att_r, n);

    cudaStreamWaitEvent(0, ev_join, 0);

    for (int l = 0; l < 3; l++) {
        int slot_in = l - 1;               // -1 = identity BN (layer 0)
        const float* gam = bn_g + (l > 0 ? (l - 1) * HID : 0);
        const float* bet = bn_b + (l > 0 ? (l - 1) * HID : 0);
        int inb = l & 1;
        if (l > 0)
            k_node_pre<<<(n * 16 + 255) / 256, 256>>>(
                att_l + l * HID, att_r + l * HID, slot_in, gam, bet, invn, inb, n);
        k_agg<<<(n + 15) / 16, 256>>>(slot_in, gam, bet, invn, l, inb, n);
    }

    // final buffer is g_b1 (agg2: in=0 -> out=1)
    k_head1<<<(bs + 63) / 64, 256>>>(W1, b1, 2, bn_g + 2 * HID, bn_b + 2 * HID, invn, bs);
    k_head2<<<(bs + 7) / 8, dim3(32, 8)>>>(W2, b2, 3, g1, be1, invbs, bs);
    k_head3<<<(bs * 32 + 255) / 256, 256>>>(W3, b3, 4, g2, be2, invbs, (float*)d_out, bs);
}